// round 17
// baseline (speedup 1.0000x reference)
#include <cuda_runtime.h>

#define IMG_H 256
#define IMG_W 256
#define KS    33
#define PADV  16
#define TX    32
#define TY    8
#define VEC   2                      // pixels per thread (float2 weight loads)
#define TILE_W (TX * VEC)            // 64
#define PW2   (TILE_W + KS - 1)      // 96 patch width
#define PLANE (IMG_H * IMG_W)        // 65536

#define PH_SUB (TY + 1)              // 9 rows: covers fh0 (ly) and fh1 (ly+1)
#define ZDIM   17                    // 16 fh-pairs + 1 single (fh=32)

__global__ void zero_out_kernel(float* __restrict__ out)
{
    int i = blockIdx.x * blockDim.x + threadIdx.x;
    ((float4*)out)[i] = make_float4(0.f, 0.f, 0.f, 0.f);
}

__global__ __launch_bounds__(TX * TY, 5)
void reblur_dynconv_pair_kernel(const float* __restrict__ img,
                                const float* __restrict__ ker,
                                float* __restrict__ out)
{
    __shared__ float s0[PH_SUB * PW2];
    __shared__ float s1[PH_SUB * PW2];
    __shared__ float s2[PH_SUB * PW2];

    const int lx  = threadIdx.x;
    const int ly  = threadIdx.y;
    const int tid = ly * TX + lx;
    const int bx0 = blockIdx.x * TILE_W;
    const int by0 = blockIdx.y * TY;
    const int fh0 = blockIdx.z * 2;          // first kernel row of the pair
    const bool two = (fh0 + 1) < KS;         // z=16 handles only fh=32

    // Stage replication-padded rows [by0+fh0-PAD, +9) x [bx0-PAD, +96), 3 ch.
    // Image is 768 KB -> all L2 hits.
    for (int i = tid; i < PH_SUB * PW2; i += TX * TY) {
        const int py = i / PW2;
        const int px = i - py * PW2;
        int gy = by0 + fh0 + py - PADV;
        int gx = bx0 + px - PADV;
        gy = gy < 0 ? 0 : (gy > IMG_H - 1 ? IMG_H - 1 : gy);
        gx = gx < 0 ? 0 : (gx > IMG_W - 1 ? IMG_W - 1 : gx);
        const int gi = gy * IMG_W + gx;
        s0[i] = img[gi];
        s1[i] = img[PLANE + gi];
        s2[i] = img[2 * PLANE + gi];
    }
    __syncthreads();

    const int x0  = bx0 + lx * VEC;
    const int y   = by0 + ly;
    const int pix = y * IMG_W + x0;

    // Two independent, interleaved weight streams (taps (fh0,fw), (fh0+1,fw)).
    const float* __restrict__ kr0 = ker + (size_t)(fh0 * KS) * PLANE + pix;
    // For the unpaired tail CTA, stream 1 re-reads stream 0's planes (valid
    // memory); its contribution is forced to zero below.
    const float* __restrict__ kr1 = two ? (kr0 + (size_t)KS * PLANE) : kr0;

    // Patch rows: fh0 -> smem row ly, fh1 -> smem row ly+1.
    const float* __restrict__ p00 = &s0[ ly      * PW2 + lx * VEC];
    const float* __restrict__ p01 = &s0[(ly + 1) * PW2 + lx * VEC];
    const float* __restrict__ p10 = &s1[ ly      * PW2 + lx * VEC];
    const float* __restrict__ p11 = &s1[(ly + 1) * PW2 + lx * VEC];
    const float* __restrict__ p20 = &s2[ ly      * PW2 + lx * VEC];
    const float* __restrict__ p21 = &s2[(ly + 1) * PW2 + lx * VEC];

    const float gate = two ? 1.0f : 0.0f;    // kills stream 1 on the tail CTA

    float a00 = 0.f, a01 = 0.f;
    float a10 = 0.f, a11 = 0.f;
    float a20 = 0.f, a21 = 0.f;

    #pragma unroll
    for (int fw = 0; fw < KS; ++fw) {
        float2 u = *(const float2*)&kr0[(size_t)fw * PLANE];  // stream 0
        float2 v = *(const float2*)&kr1[(size_t)fw * PLANE];  // stream 1

        u.x = (u.x > 1e-4f) ? u.x : 0.0f;
        u.y = (u.y > 1e-4f) ? u.y : 0.0f;
        v.x = (v.x > 1e-4f) ? v.x * gate : 0.0f;
        v.y = (v.y > 1e-4f) ? v.y * gate : 0.0f;

        a00 = fmaf(u.x, p00[fw    ], a00);
        a01 = fmaf(u.y, p00[fw + 1], a01);
        a10 = fmaf(u.x, p10[fw    ], a10);
        a11 = fmaf(u.y, p10[fw + 1], a11);
        a20 = fmaf(u.x, p20[fw    ], a20);
        a21 = fmaf(u.y, p20[fw + 1], a21);

        a00 = fmaf(v.x, p01[fw    ], a00);
        a01 = fmaf(v.y, p01[fw + 1], a01);
        a10 = fmaf(v.x, p11[fw    ], a10);
        a11 = fmaf(v.y, p11[fw + 1], a11);
        a20 = fmaf(v.x, p21[fw    ], a20);
        a21 = fmaf(v.y, p21[fw + 1], a21);
    }

    atomicAdd(&out[pix    ], a00);
    atomicAdd(&out[pix + 1], a01);

    atomicAdd(&out[PLANE + pix    ], a10);
    atomicAdd(&out[PLANE + pix + 1], a11);

    atomicAdd(&out[2 * PLANE + pix    ], a20);
    atomicAdd(&out[2 * PLANE + pix + 1], a21);
}

extern "C" void kernel_launch(void* const* d_in, const int* in_sizes, int n_in,
                              void* d_out, int out_size)
{
    const float* img = (const float*)d_in[0];   // [1,3,256,256]
    const float* ker = (const float*)d_in[1];   // [1,1089,256,256]
    float* out = (float*)d_out;                 // [1,3,256,256]

    zero_out_kernel<<<(3 * PLANE / 4) / 256, 256>>>(out);

    dim3 block(TX, TY);
    dim3 grid(IMG_W / TILE_W, IMG_H / TY, ZDIM);  // 4 x 32 x 17 = 2176 CTAs
    reblur_dynconv_pair_kernel<<<grid, block>>>(img, ker, out);
}